// round 1
// baseline (speedup 1.0000x reference)
#include <cuda_runtime.h>

// Problem constants
#define B_  1024
#define N_  128     // nodes == K (reduction dim)
#define H_  128
#define D_  8
#define HD_ (H_ * D_)            // 1024
#define BT  128                  // batch rows per block
#define CN  64                   // columns per weight chunk
#define NCHUNK_G (HD_ / CN)      // 16
#define NCHUNK_F (H_ / CN)       // 2
#define NCHUNK   (NCHUNK_G + NCHUNK_F)  // 18
#define XS_STRIDE 132            // padded row stride for transposed x tile
#define THREADS 256
#define SMEM_BYTES ((N_ * XS_STRIDE + N_ * CN) * 4)   // 67584 + 32768 = 100352

// ---- packed f32x2 helpers (sm_103a FFMA2 path) ----
__device__ __forceinline__ unsigned long long pack2(float v) {
    unsigned long long r;
    asm("mov.b64 %0, {%1, %1};" : "=l"(r) : "r"(__float_as_uint(v)));
    return r;
}
__device__ __forceinline__ void fma2(unsigned long long& d,
                                     unsigned long long a,
                                     unsigned long long b) {
    asm("fma.rn.f32x2 %0, %1, %2, %0;" : "+l"(d) : "l"(a), "l"(b));
}
__device__ __forceinline__ float2 unpack2(unsigned long long v) {
    unsigned lo, hi;
    asm("mov.b64 {%0, %1}, %2;" : "=r"(lo), "=r"(hi) : "l"(v));
    float2 f;
    f.x = __uint_as_float(lo);
    f.y = __uint_as_float(hi);
    return f;
}

__device__ __forceinline__ float elu1(float x) {
    return x > 0.0f ? x : (__expf(x) - 1.0f);
}

__global__ __launch_bounds__(THREADS, 2)
void sde_fused_kernel(const float* __restrict__ x,
                      const float* __restrict__ fw,   // [N,N,H]
                      const float* __restrict__ gw,   // [N,N,H,D]
                      const float* __restrict__ Wf,   // [N,H]
                      const float* __restrict__ bf,   // [N]
                      const float* __restrict__ Wg,   // [N,H]
                      const float* __restrict__ bg,   // [N]
                      float* __restrict__ fout,       // [B,N]
                      float* __restrict__ gout)       // [B,N,D]
{
    extern __shared__ float smem[];
    float* x_s = smem;                       // [k=128][row=128], stride 132
    float* W_s = smem + N_ * XS_STRIDE;      // [k=128][64]

    const int tid = threadIdx.x;
    const int i   = blockIdx.y;              // node
    const int b0  = blockIdx.x * BT;         // batch row base
    const int cx  = tid & 7;                 // column group (8 cols each)
    const int rx  = tid >> 3;                // row group (4 rows each)
    const int rx4 = rx * 4;
    const int cx8 = cx * 8;

    // Load x tile [BT x N] transposed into x_s[k][row]
    for (int idx = tid; idx < BT * N_; idx += THREADS) {
        int r = idx >> 7;
        int n = idx & 127;
        x_s[n * XS_STRIDE + r] = x[(size_t)(b0 + r) * N_ + n];
    }

    float accg[4][8];
    float accf[4];
#pragma unroll
    for (int r = 0; r < 4; ++r) {
        accf[r] = 0.0f;
#pragma unroll
        for (int d = 0; d < 8; ++d) accg[r][d] = 0.0f;
    }

    for (int chunk = 0; chunk < NCHUNK; ++chunk) {
        __syncthreads();   // previous chunk's compute done before overwrite

        // Load weight chunk [128 x 64]
        const float* src;
        int stride;
        if (chunk < NCHUNK_G) {
            src = gw + (size_t)i * N_ * HD_ + chunk * CN;
            stride = HD_;
        } else {
            src = fw + (size_t)i * N_ * H_ + (chunk - NCHUNK_G) * CN;
            stride = H_;
        }
        for (int idx = tid; idx < N_ * (CN / 4); idx += THREADS) {
            int n  = idx >> 4;
            int c4 = idx & 15;
            float4 v = *(const float4*)(src + (size_t)n * stride + c4 * 4);
            *(float4*)(W_s + n * CN + c4 * 4) = v;
        }
        __syncthreads();

        // 128x64 GEMM tile over K=128, packed f32x2 accumulators
        unsigned long long acc[16];
#pragma unroll
        for (int t = 0; t < 16; ++t) acc[t] = 0ull;

#pragma unroll 4
        for (int k = 0; k < N_; ++k) {
            float4 av = *(const float4*)(x_s + k * XS_STRIDE + rx4);
            const ulonglong2* wr = (const ulonglong2*)(W_s + k * CN + cx8);
            ulonglong2 p01 = wr[0];
            ulonglong2 p23 = wr[1];
            unsigned long long a0 = pack2(av.x);
            unsigned long long a1 = pack2(av.y);
            unsigned long long a2 = pack2(av.z);
            unsigned long long a3 = pack2(av.w);
            fma2(acc[0],  a0, p01.x); fma2(acc[1],  a0, p01.y);
            fma2(acc[2],  a0, p23.x); fma2(acc[3],  a0, p23.y);
            fma2(acc[4],  a1, p01.x); fma2(acc[5],  a1, p01.y);
            fma2(acc[6],  a1, p23.x); fma2(acc[7],  a1, p23.y);
            fma2(acc[8],  a2, p01.x); fma2(acc[9],  a2, p01.y);
            fma2(acc[10], a2, p23.x); fma2(acc[11], a2, p23.y);
            fma2(acc[12], a3, p01.x); fma2(acc[13], a3, p01.y);
            fma2(acc[14], a3, p23.x); fma2(acc[15], a3, p23.y);
        }

        // Epilogue: elu + weighted accumulate (registers only)
        if (chunk < NCHUNK_G) {
            // this thread's 8 columns are the 8 diffusion channels of h:
            const float w = Wg[i * H_ + chunk * 8 + cx];
#pragma unroll
            for (int r = 0; r < 4; ++r) {
#pragma unroll
                for (int p = 0; p < 4; ++p) {
                    float2 c = unpack2(acc[r * 4 + p]);
                    accg[r][2 * p]     += w * elu1(c.x);
                    accg[r][2 * p + 1] += w * elu1(c.y);
                }
            }
        } else {
            const int hb = (chunk - NCHUNK_G) * CN + cx8;
            float wf[8];
#pragma unroll
            for (int j = 0; j < 8; ++j) wf[j] = Wf[i * H_ + hb + j];
#pragma unroll
            for (int r = 0; r < 4; ++r) {
#pragma unroll
                for (int p = 0; p < 4; ++p) {
                    float2 c = unpack2(acc[r * 4 + p]);
                    accf[r] += wf[2 * p] * elu1(c.x) + wf[2 * p + 1] * elu1(c.y);
                }
            }
        }
    }

    // Reduce across the 8 column-group lanes (cx) within each octet
#pragma unroll
    for (int r = 0; r < 4; ++r) {
#pragma unroll
        for (int d = 0; d < 8; ++d) {
            float v = accg[r][d];
            v += __shfl_xor_sync(0xffffffffu, v, 1);
            v += __shfl_xor_sync(0xffffffffu, v, 2);
            v += __shfl_xor_sync(0xffffffffu, v, 4);
            accg[r][d] = v;
        }
        float vf = accf[r];
        vf += __shfl_xor_sync(0xffffffffu, vf, 1);
        vf += __shfl_xor_sync(0xffffffffu, vf, 2);
        vf += __shfl_xor_sync(0xffffffffu, vf, 4);
        accf[r] = vf;
    }

    if (cx == 0) {
        const float bgi = bg[i];
        const float bfi = bf[i];
#pragma unroll
        for (int r = 0; r < 4; ++r) {
            const int row = b0 + rx4 + r;
            fout[(size_t)row * N_ + i] = accf[r] + bfi;
            float* gp = gout + ((size_t)row * N_ + i) * D_;
#pragma unroll
            for (int d = 0; d < 8; ++d) gp[d] = accg[r][d] + bgi;
        }
    }
}

extern "C" void kernel_launch(void* const* d_in, const int* in_sizes, int n_in,
                              void* d_out, int out_size) {
    (void)in_sizes; (void)n_in; (void)out_size;
    const float* x  = (const float*)d_in[0];
    const float* fw = (const float*)d_in[1];
    const float* gw = (const float*)d_in[2];
    const float* Wf = (const float*)d_in[3];
    const float* bf = (const float*)d_in[4];
    const float* Wg = (const float*)d_in[5];
    const float* bg = (const float*)d_in[6];

    float* out  = (float*)d_out;
    float* fout = out;                       // [B,N]
    float* gout = out + (size_t)B_ * N_;     // [B,N,D]

    cudaFuncSetAttribute(sde_fused_kernel,
                         cudaFuncAttributeMaxDynamicSharedMemorySize, SMEM_BYTES);

    dim3 grid(B_ / BT, N_);
    sde_fused_kernel<<<grid, THREADS, SMEM_BYTES>>>(x, fw, gw, Wf, bf, Wg, bg,
                                                    fout, gout);
}